// round 3
// baseline (speedup 1.0000x reference)
#include <cuda_runtime.h>
#include <cuda_bf16.h>

#define NPTS 8192
#define CDIM 64
#define HEADS 4
#define KNN 16
#define DH 16

// ---------------- scratch (device globals; no allocations allowed) ----------------
__device__ float4 g_p4[NPTS];                       // x,y,z,|p|^2
__device__ float  g_xq[NPTS * CDIM];
__device__ float  g_xk[NPTS * CDIM];
__device__ float  g_xv[NPTS * CDIM];
__device__ int    g_idx[NPTS * KNN];
__device__ float  g_pe[NPTS * KNN * CDIM];          // 32 MB

// ---------------- kernel 1: pack p + squared norm ----------------
__global__ void k_prep(const float* __restrict__ p) {
    int i = blockIdx.x * blockDim.x + threadIdx.x;
    if (i < NPTS) {
        float x = p[3 * i], y = p[3 * i + 1], z = p[3 * i + 2];
        float s = x * x;
        s += y * y;
        s += z * z;
        g_p4[i] = make_float4(x, y, z, s);
    }
}

// ---------------- kernel 2: xq = x@Wq, xk = x@Wk, xv = x@Wv ----------------
// block = 256 threads, 64 rows per block, thread computes 16 rows x 1 col x 3 mats
__global__ void __launch_bounds__(256) k_proj(const float* __restrict__ x,
                                              const float* __restrict__ Wq,
                                              const float* __restrict__ Wk,
                                              const float* __restrict__ Wv) {
    __shared__ float xs[64][65];
    int t = threadIdx.x;
    int row0 = blockIdx.x * 64;
    for (int i = t; i < 64 * 64; i += 256)
        xs[i >> 6][i & 63] = x[(row0 + (i >> 6)) * 64 + (i & 63)];
    __syncthreads();

    int c = t & 63;
    int rg = t >> 6;   // 0..3, rows rg*16 .. rg*16+15
    float aq[16], ak[16], av[16];
#pragma unroll
    for (int r = 0; r < 16; ++r) { aq[r] = 0.f; ak[r] = 0.f; av[r] = 0.f; }

    for (int k = 0; k < 64; ++k) {
        float wq = __ldg(&Wq[k * 64 + c]);
        float wk = __ldg(&Wk[k * 64 + c]);
        float wv = __ldg(&Wv[k * 64 + c]);
#pragma unroll
        for (int r = 0; r < 16; ++r) {
            float xv = xs[rg * 16 + r][k];
            aq[r] = fmaf(xv, wq, aq[r]);
            ak[r] = fmaf(xv, wk, ak[r]);
            av[r] = fmaf(xv, wv, av[r]);
        }
    }
#pragma unroll
    for (int r = 0; r < 16; ++r) {
        int row = row0 + rg * 16 + r;
        g_xq[row * 64 + c] = aq[r];
        g_xk[row * 64 + c] = ak[r];
        g_xv[row * 64 + c] = av[r];
    }
}

// ---------------- kernel 3: exact KNN top-16 ----------------
// warp per query. 64-bit key = orderable(d2) << 32 | j  -> matches jax stable top_k.
__device__ __forceinline__ unsigned order_float(float f) {
    unsigned b = __float_as_uint(f);
    return (b & 0x80000000u) ? ~b : (b | 0x80000000u);
}

__global__ void __launch_bounds__(256) k_knn() {
    __shared__ unsigned long long buf[8][512];   // per warp: 32 lanes * 16, transposed
    int gw = (blockIdx.x * blockDim.x + threadIdx.x) >> 5;   // query id
    int lane = threadIdx.x & 31;
    int w = threadIdx.x >> 5;
    if (gw >= NPTS) return;

    float4 q = g_p4[gw];
    unsigned long long lst[16];
#pragma unroll
    for (int i = 0; i < 16; ++i) lst[i] = ~0ULL;

    for (int j = lane; j < NPTS; j += 32) {
        float4 cnd = __ldg(&g_p4[j]);
        float dot = q.x * cnd.x;
        dot = fmaf(q.y, cnd.y, dot);
        dot = fmaf(q.z, cnd.z, dot);
        float d2 = (q.w + cnd.w) - 2.0f * dot;
        unsigned long long key =
            ((unsigned long long)order_float(d2) << 32) | (unsigned)j;
        if (key < lst[15]) {
            lst[15] = key;
#pragma unroll
            for (int s = 15; s >= 1; --s) {
                unsigned long long a = lst[s - 1], b = lst[s];
                bool sw = b < a;
                lst[s - 1] = sw ? b : a;
                lst[s] = sw ? a : b;
            }
        }
    }

    // write transposed (conflict-free) and merge: 16 rounds of warp argmin
    unsigned long long* mb = buf[w];
#pragma unroll
    for (int i = 0; i < 16; ++i) mb[i * 32 + lane] = lst[i];
    __syncwarp();

    int pos = 0;
    for (int r = 0; r < KNN; ++r) {
        unsigned long long cand = (pos < 16) ? mb[pos * 32 + lane] : ~0ULL;
        unsigned long long m = cand;
#pragma unroll
        for (int off = 16; off; off >>= 1) {
            unsigned long long o = __shfl_xor_sync(0xffffffffu, m, off);
            if (o < m) m = o;
        }
        unsigned msk = __ballot_sync(0xffffffffu, cand == m);
        int owner = __ffs(msk) - 1;
        if (lane == owner) pos++;
        if (lane == 0) g_idx[gw * KNN + r] = (int)(unsigned)(m & 0xffffffffu);
    }
}

// ---------------- kernel 4: PPF features + pe MLP ----------------
__device__ __forceinline__ float angle_f(float ux, float uy, float uz,
                                         float vx, float vy, float vz) {
    float cx = uy * vz - uz * vy;
    float cy = uz * vx - ux * vz;
    float cz = ux * vy - uy * vx;
    float s = sqrtf(cx * cx + cy * cy + cz * cz + 1e-9f);
    float c = ux * vx + uy * vy + uz * vz;
    return atan2f(s, c);
}

// block = 256 threads handles 64 (n,kk) rows
__global__ void __launch_bounds__(256) k_ppf(const float* __restrict__ p,
                                             const float* __restrict__ nrm,
                                             const float* __restrict__ W1,
                                             const float* __restrict__ b1,
                                             const float* __restrict__ W2,
                                             const float* __restrict__ b2) {
    __shared__ float ppfs[64][4];
    __shared__ float hs[64][65];
    int t = threadIdx.x;
    int base = blockIdx.x * 64;   // global row = n*16 + kk

    // stage A: PPF (threads 0..63, one row each)
    if (t < 64) {
        int gr = base + t;
        int n = gr >> 4;
        int j = g_idx[gr];
        float px = p[3 * n], py = p[3 * n + 1], pz = p[3 * n + 2];
        float dx = p[3 * j] - px, dy = p[3 * j + 1] - py, dz = p[3 * j + 2] - pz;
        float ncx = nrm[3 * n], ncy = nrm[3 * n + 1], ncz = nrm[3 * n + 2];
        float nrx = nrm[3 * j], nry = nrm[3 * j + 1], nrz = nrm[3 * j + 2];
        ppfs[t][0] = angle_f(ncx, ncy, ncz, dx, dy, dz);
        ppfs[t][1] = angle_f(nrx, nry, nrz, dx, dy, dz);
        ppfs[t][2] = angle_f(ncx, ncy, ncz, nrx, nry, nrz);
        ppfs[t][3] = sqrtf(dx * dx + dy * dy + dz * dz + 1e-9f);
    }
    __syncthreads();

    // stage B: h = relu(ppf @ W1 + b1); thread: col c, 16 rows
    {
        int c = t & 63;
        int rg = t >> 6;
        float w0 = __ldg(&W1[0 * 64 + c]);
        float w1v = __ldg(&W1[1 * 64 + c]);
        float w2v = __ldg(&W1[2 * 64 + c]);
        float w3 = __ldg(&W1[3 * 64 + c]);
        float bb = __ldg(&b1[c]);
#pragma unroll
        for (int i = 0; i < 16; ++i) {
            int r = rg + 4 * i;
            float v = bb;
            v = fmaf(ppfs[r][0], w0, v);
            v = fmaf(ppfs[r][1], w1v, v);
            v = fmaf(ppfs[r][2], w2v, v);
            v = fmaf(ppfs[r][3], w3, v);
            hs[r][c] = fmaxf(v, 0.f);
        }
    }
    __syncthreads();

    // stage C: pe = h @ W2 + b2; 4x4 register tile per thread
    {
        int rg = t >> 4;          // 0..15 -> rows rg*4..rg*4+3
        int cg = t & 15;          // cols cg*4..cg*4+3
        float acc[4][4];
#pragma unroll
        for (int a = 0; a < 4; ++a)
#pragma unroll
            for (int b = 0; b < 4; ++b) acc[a][b] = 0.f;
        for (int k = 0; k < 64; ++k) {
            float4 wv = __ldg((const float4*)&W2[k * 64 + cg * 4]);
            float h0 = hs[rg * 4 + 0][k];
            float h1 = hs[rg * 4 + 1][k];
            float h2 = hs[rg * 4 + 2][k];
            float h3 = hs[rg * 4 + 3][k];
            acc[0][0] = fmaf(h0, wv.x, acc[0][0]); acc[0][1] = fmaf(h0, wv.y, acc[0][1]);
            acc[0][2] = fmaf(h0, wv.z, acc[0][2]); acc[0][3] = fmaf(h0, wv.w, acc[0][3]);
            acc[1][0] = fmaf(h1, wv.x, acc[1][0]); acc[1][1] = fmaf(h1, wv.y, acc[1][1]);
            acc[1][2] = fmaf(h1, wv.z, acc[1][2]); acc[1][3] = fmaf(h1, wv.w, acc[1][3]);
            acc[2][0] = fmaf(h2, wv.x, acc[2][0]); acc[2][1] = fmaf(h2, wv.y, acc[2][1]);
            acc[2][2] = fmaf(h2, wv.z, acc[2][2]); acc[2][3] = fmaf(h2, wv.w, acc[2][3]);
            acc[3][0] = fmaf(h3, wv.x, acc[3][0]); acc[3][1] = fmaf(h3, wv.y, acc[3][1]);
            acc[3][2] = fmaf(h3, wv.z, acc[3][2]); acc[3][3] = fmaf(h3, wv.w, acc[3][3]);
        }
        float4 bv = __ldg((const float4*)&b2[cg * 4]);
#pragma unroll
        for (int a = 0; a < 4; ++a) {
            int row = base + rg * 4 + a;
            float4 o;
            o.x = acc[a][0] + bv.x; o.y = acc[a][1] + bv.y;
            o.z = acc[a][2] + bv.z; o.w = acc[a][3] + bv.w;
            *(float4*)&g_pe[row * 64 + cg * 4] = o;
        }
    }
}

// ---------------- kernel 5: attention + Wo + LN + residual + relu ----------------
// block = 256 threads = 4 points x 64 threads (thread = channel)
__global__ void __launch_bounds__(256) k_attn(const float* __restrict__ x,
                                              const float* __restrict__ Wo,
                                              const float* __restrict__ lng,
                                              const float* __restrict__ lnb,
                                              float* __restrict__ out) {
    __shared__ float vbuf[4][16][64];
    __shared__ float sl[4][4][16];
    __shared__ float wb[4][4][16];
    __shared__ float obuf[4][64];
    __shared__ float redA[4][2], redB[4][2];
    __shared__ int sidx[4][16];

    int pt = threadIdx.x >> 6;
    int t = threadIdx.x & 63;
    int n = blockIdx.x * 4 + pt;
    int h = t >> 4;

    if (t < 16) sidx[pt][t] = g_idx[n * KNN + t];
    __syncthreads();

    float qv = g_xq[n * 64 + t];

    for (int kk = 0; kk < 16; ++kk) {
        int j = sidx[pt][kk];
        float pe = g_pe[(n * KNN + kk) * 64 + t];
        float kvv = g_xk[j * 64 + t] + pe;
        float vvv = g_xv[j * 64 + t] + pe;
        vbuf[pt][kk][t] = vvv;
        float prod = qv * kvv;
#pragma unroll
        for (int off = 8; off; off >>= 1)
            prod += __shfl_xor_sync(0xffffffffu, prod, off);
        if ((t & 15) == 0) sl[pt][h][kk] = prod;
    }
    __syncthreads();

    if (t < 4) {
        float mx = -1e30f;
        float e[16];
#pragma unroll
        for (int kk = 0; kk < 16; ++kk) {
            float v = sl[pt][t][kk] * 0.25f;
            e[kk] = v;
            mx = fmaxf(mx, v);
        }
        float s = 0.f;
#pragma unroll
        for (int kk = 0; kk < 16; ++kk) { e[kk] = expf(e[kk] - mx); s += e[kk]; }
        float inv = 1.f / s;
#pragma unroll
        for (int kk = 0; kk < 16; ++kk) wb[pt][t][kk] = e[kk] * inv;
    }
    __syncthreads();

    float o = 0.f;
#pragma unroll
    for (int kk = 0; kk < 16; ++kk)
        o = fmaf(wb[pt][h][kk], vbuf[pt][kk][t], o);
    obuf[pt][t] = o;
    __syncthreads();

    float y = 0.f;
#pragma unroll 8
    for (int c = 0; c < 64; ++c)
        y = fmaf(obuf[pt][c], __ldg(&Wo[c * 64 + t]), y);

    // LayerNorm over 64 channels (2 warps per point)
    float s1 = y, s2 = y * y;
#pragma unroll
    for (int off = 16; off; off >>= 1) {
        s1 += __shfl_xor_sync(0xffffffffu, s1, off);
        s2 += __shfl_xor_sync(0xffffffffu, s2, off);
    }
    int wip = t >> 5;
    if ((t & 31) == 0) { redA[pt][wip] = s1; redB[pt][wip] = s2; }
    __syncthreads();
    float sum = redA[pt][0] + redA[pt][1];
    float sumsq = redB[pt][0] + redB[pt][1];
    float mu = sum * (1.f / 64.f);
    float var = fmaxf(sumsq * (1.f / 64.f) - mu * mu, 0.f);
    float yn = (y - mu) * rsqrtf(var + 1e-5f) * __ldg(&lng[t]) + __ldg(&lnb[t]);
    float res = yn + x[n * 64 + t];
    out[n * 64 + t] = fmaxf(res, 0.f);
}

// ---------------- launch ----------------
extern "C" void kernel_launch(void* const* d_in, const int* in_sizes, int n_in,
                              void* d_out, int out_size) {
    const float* p    = (const float*)d_in[0];
    const float* x    = (const float*)d_in[1];
    const float* nrm  = (const float*)d_in[2];
    const float* Wq   = (const float*)d_in[3];
    const float* Wk   = (const float*)d_in[4];
    const float* Wv   = (const float*)d_in[5];
    const float* Wo   = (const float*)d_in[6];
    const float* w1   = (const float*)d_in[7];
    const float* b1   = (const float*)d_in[8];
    const float* w2   = (const float*)d_in[9];
    const float* b2   = (const float*)d_in[10];
    const float* lng  = (const float*)d_in[11];
    const float* lnb  = (const float*)d_in[12];
    float* out = (float*)d_out;

    k_prep<<<NPTS / 256, 256>>>(p);
    k_proj<<<NPTS / 64, 256>>>(x, Wq, Wk, Wv);
    k_knn<<<NPTS / 8, 256>>>();
    k_ppf<<<NPTS * KNN / 64, 256>>>(p, nrm, w1, b1, w2, b2);
    k_attn<<<NPTS / 4, 256>>>(x, Wo, lng, lnb, out);
}

// round 4
// speedup vs baseline: 1.0409x; 1.0409x over previous
#include <cuda_runtime.h>
#include <cuda_bf16.h>

#define NPTS 8192
#define CDIM 64
#define HEADS 4
#define KNN 16
#define DH 16

// ---------------- scratch (device globals; no allocations allowed) ----------------
__device__ float4 g_p4[NPTS];                       // x,y,z,|p|^2
__device__ float  g_xq[NPTS * CDIM];
__device__ float  g_xk[NPTS * CDIM];
__device__ float  g_xv[NPTS * CDIM];
__device__ int    g_idx[NPTS * KNN];
__device__ float  g_pe[NPTS * KNN * CDIM];          // 32 MB

// ---------------- kernel 1: pack p + squared norm ----------------
__global__ void k_prep(const float* __restrict__ p) {
    int i = blockIdx.x * blockDim.x + threadIdx.x;
    if (i < NPTS) {
        float x = p[3 * i], y = p[3 * i + 1], z = p[3 * i + 2];
        float s = x * x;
        s += y * y;
        s += z * z;
        g_p4[i] = make_float4(x, y, z, s);
    }
}

// ---------------- kernel 2: xq = x@Wq, xk = x@Wk, xv = x@Wv ----------------
__global__ void __launch_bounds__(256) k_proj(const float* __restrict__ x,
                                              const float* __restrict__ Wq,
                                              const float* __restrict__ Wk,
                                              const float* __restrict__ Wv) {
    __shared__ float xs[64][65];
    int t = threadIdx.x;
    int row0 = blockIdx.x * 64;
    for (int i = t; i < 64 * 64; i += 256)
        xs[i >> 6][i & 63] = x[(row0 + (i >> 6)) * 64 + (i & 63)];
    __syncthreads();

    int c = t & 63;
    int rg = t >> 6;   // 0..3, rows rg*16 .. rg*16+15
    float aq[16], ak[16], av[16];
#pragma unroll
    for (int r = 0; r < 16; ++r) { aq[r] = 0.f; ak[r] = 0.f; av[r] = 0.f; }

    for (int k = 0; k < 64; ++k) {
        float wq = __ldg(&Wq[k * 64 + c]);
        float wk = __ldg(&Wk[k * 64 + c]);
        float wv = __ldg(&Wv[k * 64 + c]);
#pragma unroll
        for (int r = 0; r < 16; ++r) {
            float xv = xs[rg * 16 + r][k];
            aq[r] = fmaf(xv, wq, aq[r]);
            ak[r] = fmaf(xv, wk, ak[r]);
            av[r] = fmaf(xv, wv, av[r]);
        }
    }
#pragma unroll
    for (int r = 0; r < 16; ++r) {
        int row = row0 + rg * 16 + r;
        g_xq[row * 64 + c] = aq[r];
        g_xk[row * 64 + c] = ak[r];
        g_xv[row * 64 + c] = av[r];
    }
}

// ---------------- kernel 3: exact KNN top-16, threshold-pruned ----------------
// warp per query. 64-bit key = orderable(d2) << 32 | j  -> matches jax stable top_k.
// Pruning: tau = warp-min of lst[15] is an upper bound of the final global 16th
// key, so candidates with key >= tau can never enter the global top-16.
__device__ __forceinline__ unsigned order_float(float f) {
    unsigned b = __float_as_uint(f);
    return (b & 0x80000000u) ? ~b : (b | 0x80000000u);
}

#define KNN_TILE 512

__global__ void __launch_bounds__(256) k_knn() {
    __shared__ float4 cbuf[KNN_TILE];                // 8 KB candidate tile
    __shared__ unsigned long long buf[8][512];       // 32 KB merge scratch
    int lane = threadIdx.x & 31;
    int w = threadIdx.x >> 5;
    int t = threadIdx.x;
    int gw = blockIdx.x * 8 + w;                     // query id

    float4 q = g_p4[gw];
    unsigned long long lst[16];
#pragma unroll
    for (int i = 0; i < 16; ++i) lst[i] = ~0ULL;

    for (int tile = 0; tile < NPTS; tile += KNN_TILE) {
        __syncthreads();
        cbuf[t]       = __ldg(&g_p4[tile + t]);
        cbuf[t + 256] = __ldg(&g_p4[tile + t + 256]);
        __syncthreads();

        // refresh warp threshold
        unsigned long long tau = lst[15];
#pragma unroll
        for (int off = 16; off; off >>= 1) {
            unsigned long long o = __shfl_xor_sync(0xffffffffu, tau, off);
            if (o < tau) tau = o;
        }

#pragma unroll 4
        for (int u = 0; u < KNN_TILE / 32; ++u) {
            int j = tile + u * 32 + lane;
            float4 cnd = cbuf[u * 32 + lane];
            float dot = q.x * cnd.x;
            dot = fmaf(q.y, cnd.y, dot);
            dot = fmaf(q.z, cnd.z, dot);
            float d2 = (q.w + cnd.w) - 2.0f * dot;
            unsigned long long key =
                ((unsigned long long)order_float(d2) << 32) | (unsigned)j;
            if (key < tau && key < lst[15]) {
                lst[15] = key;
#pragma unroll
                for (int s = 15; s >= 1; --s) {
                    unsigned long long a = lst[s - 1], b = lst[s];
                    bool sw = b < a;
                    lst[s - 1] = sw ? b : a;
                    lst[s] = sw ? a : b;
                }
            }
        }
    }

    // write transposed (conflict-free) and merge: 16 rounds of warp argmin
    unsigned long long* mb = buf[w];
#pragma unroll
    for (int i = 0; i < 16; ++i) mb[i * 32 + lane] = lst[i];
    __syncwarp();

    int pos = 0;
    for (int r = 0; r < KNN; ++r) {
        unsigned long long cand = (pos < 16) ? mb[pos * 32 + lane] : ~0ULL;
        unsigned long long m = cand;
#pragma unroll
        for (int off = 16; off; off >>= 1) {
            unsigned long long o = __shfl_xor_sync(0xffffffffu, m, off);
            if (o < m) m = o;
        }
        unsigned msk = __ballot_sync(0xffffffffu, cand == m);
        int owner = __ffs(msk) - 1;
        if (lane == owner) pos++;
        if (lane == 0) g_idx[gw * KNN + r] = (int)(unsigned)(m & 0xffffffffu);
    }
}

// ---------------- kernel 4: PPF features + pe MLP ----------------
__device__ __forceinline__ float angle_f(float ux, float uy, float uz,
                                         float vx, float vy, float vz) {
    float cx = uy * vz - uz * vy;
    float cy = uz * vx - ux * vz;
    float cz = ux * vy - uy * vx;
    float s = sqrtf(cx * cx + cy * cy + cz * cz + 1e-9f);
    float c = ux * vx + uy * vy + uz * vz;
    return atan2f(s, c);
}

// block = 256 threads handles 64 (n,kk) rows
__global__ void __launch_bounds__(256) k_ppf(const float* __restrict__ p,
                                             const float* __restrict__ nrm,
                                             const float* __restrict__ W1,
                                             const float* __restrict__ b1,
                                             const float* __restrict__ W2,
                                             const float* __restrict__ b2) {
    __shared__ float ppfs[64][4];
    __shared__ float hs[64][65];
    int t = threadIdx.x;
    int base = blockIdx.x * 64;   // global row = n*16 + kk

    // stage A: PPF (threads 0..63, one row each)
    if (t < 64) {
        int gr = base + t;
        int n = gr >> 4;
        int j = g_idx[gr];
        float px = p[3 * n], py = p[3 * n + 1], pz = p[3 * n + 2];
        float dx = p[3 * j] - px, dy = p[3 * j + 1] - py, dz = p[3 * j + 2] - pz;
        float ncx = nrm[3 * n], ncy = nrm[3 * n + 1], ncz = nrm[3 * n + 2];
        float nrx = nrm[3 * j], nry = nrm[3 * j + 1], nrz = nrm[3 * j + 2];
        ppfs[t][0] = angle_f(ncx, ncy, ncz, dx, dy, dz);
        ppfs[t][1] = angle_f(nrx, nry, nrz, dx, dy, dz);
        ppfs[t][2] = angle_f(ncx, ncy, ncz, nrx, nry, nrz);
        ppfs[t][3] = sqrtf(dx * dx + dy * dy + dz * dz + 1e-9f);
    }
    __syncthreads();

    // stage B: h = relu(ppf @ W1 + b1); thread: col c, 16 rows
    {
        int c = t & 63;
        int rg = t >> 6;
        float w0 = __ldg(&W1[0 * 64 + c]);
        float w1v = __ldg(&W1[1 * 64 + c]);
        float w2v = __ldg(&W1[2 * 64 + c]);
        float w3 = __ldg(&W1[3 * 64 + c]);
        float bb = __ldg(&b1[c]);
#pragma unroll
        for (int i = 0; i < 16; ++i) {
            int r = rg + 4 * i;
            float v = bb;
            v = fmaf(ppfs[r][0], w0, v);
            v = fmaf(ppfs[r][1], w1v, v);
            v = fmaf(ppfs[r][2], w2v, v);
            v = fmaf(ppfs[r][3], w3, v);
            hs[r][c] = fmaxf(v, 0.f);
        }
    }
    __syncthreads();

    // stage C: pe = h @ W2 + b2; 4x4 register tile per thread
    {
        int rg = t >> 4;          // 0..15 -> rows rg*4..rg*4+3
        int cg = t & 15;          // cols cg*4..cg*4+3
        float acc[4][4];
#pragma unroll
        for (int a = 0; a < 4; ++a)
#pragma unroll
            for (int b = 0; b < 4; ++b) acc[a][b] = 0.f;
        for (int k = 0; k < 64; ++k) {
            float4 wv = __ldg((const float4*)&W2[k * 64 + cg * 4]);
            float h0 = hs[rg * 4 + 0][k];
            float h1 = hs[rg * 4 + 1][k];
            float h2 = hs[rg * 4 + 2][k];
            float h3 = hs[rg * 4 + 3][k];
            acc[0][0] = fmaf(h0, wv.x, acc[0][0]); acc[0][1] = fmaf(h0, wv.y, acc[0][1]);
            acc[0][2] = fmaf(h0, wv.z, acc[0][2]); acc[0][3] = fmaf(h0, wv.w, acc[0][3]);
            acc[1][0] = fmaf(h1, wv.x, acc[1][0]); acc[1][1] = fmaf(h1, wv.y, acc[1][1]);
            acc[1][2] = fmaf(h1, wv.z, acc[1][2]); acc[1][3] = fmaf(h1, wv.w, acc[1][3]);
            acc[2][0] = fmaf(h2, wv.x, acc[2][0]); acc[2][1] = fmaf(h2, wv.y, acc[2][1]);
            acc[2][2] = fmaf(h2, wv.z, acc[2][2]); acc[2][3] = fmaf(h2, wv.w, acc[2][3]);
            acc[3][0] = fmaf(h3, wv.x, acc[3][0]); acc[3][1] = fmaf(h3, wv.y, acc[3][1]);
            acc[3][2] = fmaf(h3, wv.z, acc[3][2]); acc[3][3] = fmaf(h3, wv.w, acc[3][3]);
        }
        float4 bv = __ldg((const float4*)&b2[cg * 4]);
#pragma unroll
        for (int a = 0; a < 4; ++a) {
            int row = base + rg * 4 + a;
            float4 o;
            o.x = acc[a][0] + bv.x; o.y = acc[a][1] + bv.y;
            o.z = acc[a][2] + bv.z; o.w = acc[a][3] + bv.w;
            *(float4*)&g_pe[row * 64 + cg * 4] = o;
        }
    }
}

// ---------------- kernel 5: attention + Wo + LN + residual + relu ----------------
__global__ void __launch_bounds__(256) k_attn(const float* __restrict__ x,
                                              const float* __restrict__ Wo,
                                              const float* __restrict__ lng,
                                              const float* __restrict__ lnb,
                                              float* __restrict__ out) {
    __shared__ float vbuf[4][16][64];
    __shared__ float sl[4][4][16];
    __shared__ float wb[4][4][16];
    __shared__ float obuf[4][64];
    __shared__ float redA[4][2], redB[4][2];
    __shared__ int sidx[4][16];

    int pt = threadIdx.x >> 6;
    int t = threadIdx.x & 63;
    int n = blockIdx.x * 4 + pt;
    int h = t >> 4;

    if (t < 16) sidx[pt][t] = g_idx[n * KNN + t];
    __syncthreads();

    float qv = g_xq[n * 64 + t];

    for (int kk = 0; kk < 16; ++kk) {
        int j = sidx[pt][kk];
        float pe = g_pe[(n * KNN + kk) * 64 + t];
        float kvv = g_xk[j * 64 + t] + pe;
        float vvv = g_xv[j * 64 + t] + pe;
        vbuf[pt][kk][t] = vvv;
        float prod = qv * kvv;
#pragma unroll
        for (int off = 8; off; off >>= 1)
            prod += __shfl_xor_sync(0xffffffffu, prod, off);
        if ((t & 15) == 0) sl[pt][h][kk] = prod;
    }
    __syncthreads();

    if (t < 4) {
        float mx = -1e30f;
        float e[16];
#pragma unroll
        for (int kk = 0; kk < 16; ++kk) {
            float v = sl[pt][t][kk] * 0.25f;
            e[kk] = v;
            mx = fmaxf(mx, v);
        }
        float s = 0.f;
#pragma unroll
        for (int kk = 0; kk < 16; ++kk) { e[kk] = expf(e[kk] - mx); s += e[kk]; }
        float inv = 1.f / s;
#pragma unroll
        for (int kk = 0; kk < 16; ++kk) wb[pt][t][kk] = e[kk] * inv;
    }
    __syncthreads();

    float o = 0.f;
#pragma unroll
    for (int kk = 0; kk < 16; ++kk)
        o = fmaf(wb[pt][h][kk], vbuf[pt][kk][t], o);
    obuf[pt][t] = o;
    __syncthreads();

    float y = 0.f;
#pragma unroll 8
    for (int c = 0; c < 64; ++c)
        y = fmaf(obuf[pt][c], __ldg(&Wo[c * 64 + t]), y);

    // LayerNorm over 64 channels (2 warps per point)
    float s1 = y, s2 = y * y;
#pragma unroll
    for (int off = 16; off; off >>= 1) {
        s1 += __shfl_xor_sync(0xffffffffu, s1, off);
        s2 += __shfl_xor_sync(0xffffffffu, s2, off);
    }
    int wip = t >> 5;
    if ((t & 31) == 0) { redA[pt][wip] = s1; redB[pt][wip] = s2; }
    __syncthreads();
    float sum = redA[pt][0] + redA[pt][1];
    float sumsq = redB[pt][0] + redB[pt][1];
    float mu = sum * (1.f / 64.f);
    float var = fmaxf(sumsq * (1.f / 64.f) - mu * mu, 0.f);
    float yn = (y - mu) * rsqrtf(var + 1e-5f) * __ldg(&lng[t]) + __ldg(&lnb[t]);
    float res = yn + x[n * 64 + t];
    out[n * 64 + t] = fmaxf(res, 0.f);
}

// ---------------- launch ----------------
extern "C" void kernel_launch(void* const* d_in, const int* in_sizes, int n_in,
                              void* d_out, int out_size) {
    const float* p    = (const float*)d_in[0];
    const float* x    = (const float*)d_in[1];
    const float* nrm  = (const float*)d_in[2];
    const float* Wq   = (const float*)d_in[3];
    const float* Wk   = (const float*)d_in[4];
    const float* Wv   = (const float*)d_in[5];
    const float* Wo   = (const float*)d_in[6];
    const float* w1   = (const float*)d_in[7];
    const float* b1   = (const float*)d_in[8];
    const float* w2   = (const float*)d_in[9];
    const float* b2   = (const float*)d_in[10];
    const float* lng  = (const float*)d_in[11];
    const float* lnb  = (const float*)d_in[12];
    float* out = (float*)d_out;

    k_prep<<<NPTS / 256, 256>>>(p);
    k_proj<<<NPTS / 64, 256>>>(x, Wq, Wk, Wv);
    k_knn<<<NPTS / 8, 256>>>();
    k_ppf<<<NPTS * KNN / 64, 256>>>(p, nrm, w1, b1, w2, b2);
    k_attn<<<NPTS / 4, 256>>>(x, Wo, lng, lnb, out);
}

// round 5
// speedup vs baseline: 3.1697x; 3.0451x over previous
#include <cuda_runtime.h>
#include <cuda_bf16.h>

#define NPTS 8192
#define CDIM 64
#define HEADS 4
#define KNN 16
#define DH 16
#define FULLMASK 0xffffffffu

// ---------------- scratch (device globals; no allocations allowed) ----------------
__device__ float4 g_p4[NPTS];                       // x,y,z,|p|^2
__device__ float  g_xq[NPTS * CDIM];
__device__ float  g_xk[NPTS * CDIM];
__device__ float  g_xv[NPTS * CDIM];
__device__ int    g_idx[NPTS * KNN];
__device__ float  g_pe[NPTS * KNN * CDIM];          // 32 MB

// ---------------- kernel 1: pack p + squared norm ----------------
__global__ void k_prep(const float* __restrict__ p) {
    int i = blockIdx.x * blockDim.x + threadIdx.x;
    if (i < NPTS) {
        float x = p[3 * i], y = p[3 * i + 1], z = p[3 * i + 2];
        float s = x * x;
        s += y * y;
        s += z * z;
        g_p4[i] = make_float4(x, y, z, s);
    }
}

// ---------------- kernel 2: xq = x@Wq, xk = x@Wk, xv = x@Wv ----------------
__global__ void __launch_bounds__(256) k_proj(const float* __restrict__ x,
                                              const float* __restrict__ Wq,
                                              const float* __restrict__ Wk,
                                              const float* __restrict__ Wv) {
    __shared__ float xs[64][65];
    int t = threadIdx.x;
    int row0 = blockIdx.x * 64;
    for (int i = t; i < 64 * 64; i += 256)
        xs[i >> 6][i & 63] = x[(row0 + (i >> 6)) * 64 + (i & 63)];
    __syncthreads();

    int c = t & 63;
    int rg = t >> 6;   // 0..3, rows rg*16 .. rg*16+15
    float aq[16], ak[16], av[16];
#pragma unroll
    for (int r = 0; r < 16; ++r) { aq[r] = 0.f; ak[r] = 0.f; av[r] = 0.f; }

    for (int k = 0; k < 64; ++k) {
        float wq = __ldg(&Wq[k * 64 + c]);
        float wk = __ldg(&Wk[k * 64 + c]);
        float wv = __ldg(&Wv[k * 64 + c]);
#pragma unroll
        for (int r = 0; r < 16; ++r) {
            float xv = xs[rg * 16 + r][k];
            aq[r] = fmaf(xv, wq, aq[r]);
            ak[r] = fmaf(xv, wk, ak[r]);
            av[r] = fmaf(xv, wv, av[r]);
        }
    }
#pragma unroll
    for (int r = 0; r < 16; ++r) {
        int row = row0 + rg * 16 + r;
        g_xq[row * 64 + c] = aq[r];
        g_xk[row * 64 + c] = ak[r];
        g_xv[row * 64 + c] = av[r];
    }
}

// ---------------- kernel 3: exact KNN top-16 via warp-distributed sorted list ----------------
// Lane l (l<16) holds the l-th smallest key seen so far by the whole warp.
// tau = best[15] is the exact running global 16th best -> tightest filter.
// Inserts are warp-uniform (all lanes participate), so no divergence penalty.
__device__ __forceinline__ unsigned order_float(float f) {
    unsigned b = __float_as_uint(f);
    return (b & 0x80000000u) ? ~b : (b | 0x80000000u);
}

#define KNN_TILE 512

__global__ void __launch_bounds__(256) k_knn() {
    __shared__ float4 cbuf[KNN_TILE];                // 8 KB candidate tile
    int lane = threadIdx.x & 31;
    int w = threadIdx.x >> 5;
    int t = threadIdx.x;
    int gw = blockIdx.x * 8 + w;                     // query id

    float4 q = g_p4[gw];
    unsigned long long best = ~0ULL;                 // distributed sorted list
    unsigned long long tau = ~0ULL;

    for (int tile = 0; tile < NPTS; tile += KNN_TILE) {
        __syncthreads();
        cbuf[t]       = __ldg(&g_p4[tile + t]);
        cbuf[t + 256] = __ldg(&g_p4[tile + t + 256]);
        __syncthreads();

#pragma unroll 4
        for (int u = 0; u < KNN_TILE / 32; ++u) {
            int j = tile + u * 32 + lane;
            float4 cnd = cbuf[u * 32 + lane];
            float dot = q.x * cnd.x;
            dot = fmaf(q.y, cnd.y, dot);
            dot = fmaf(q.z, cnd.z, dot);
            float d2 = (q.w + cnd.w) - 2.0f * dot;
            unsigned long long key =
                ((unsigned long long)order_float(d2) << 32) | (unsigned)j;

            unsigned pend = __ballot_sync(FULLMASK, key < tau);
            while (pend) {
                int src = __ffs(pend) - 1;
                unsigned long long vb = __shfl_sync(FULLMASK, key, src);
                unsigned long long up = __shfl_up_sync(FULLMASK, best, 1);
                bool lt = vb < best;
                unsigned m = __ballot_sync(FULLMASK, lt);
                int fl = __ffs(m) - 1;
                if (lt) best = (lane == fl) ? vb : up;
                tau = __shfl_sync(FULLMASK, best, 15);
                pend &= pend - 1;
                pend &= __ballot_sync(FULLMASK, key < tau);
            }
        }
    }

    if (lane < KNN)
        g_idx[gw * KNN + lane] = (int)(unsigned)(best & 0xffffffffu);
}

// ---------------- kernel 4: PPF features + pe MLP ----------------
__device__ __forceinline__ float angle_f(float ux, float uy, float uz,
                                         float vx, float vy, float vz) {
    float cx = uy * vz - uz * vy;
    float cy = uz * vx - ux * vz;
    float cz = ux * vy - uy * vx;
    float s = sqrtf(cx * cx + cy * cy + cz * cz + 1e-9f);
    float c = ux * vx + uy * vy + uz * vz;
    return atan2f(s, c);
}

// block = 256 threads handles 64 (n,kk) rows
__global__ void __launch_bounds__(256) k_ppf(const float* __restrict__ p,
                                             const float* __restrict__ nrm,
                                             const float* __restrict__ W1,
                                             const float* __restrict__ b1,
                                             const float* __restrict__ W2,
                                             const float* __restrict__ b2) {
    __shared__ float ppfs[64][4];
    __shared__ float hs[64][65];
    int t = threadIdx.x;
    int base = blockIdx.x * 64;   // global row = n*16 + kk

    // stage A: PPF (threads 0..63, one row each)
    if (t < 64) {
        int gr = base + t;
        int n = gr >> 4;
        int j = g_idx[gr];
        float px = p[3 * n], py = p[3 * n + 1], pz = p[3 * n + 2];
        float dx = p[3 * j] - px, dy = p[3 * j + 1] - py, dz = p[3 * j + 2] - pz;
        float ncx = nrm[3 * n], ncy = nrm[3 * n + 1], ncz = nrm[3 * n + 2];
        float nrx = nrm[3 * j], nry = nrm[3 * j + 1], nrz = nrm[3 * j + 2];
        ppfs[t][0] = angle_f(ncx, ncy, ncz, dx, dy, dz);
        ppfs[t][1] = angle_f(nrx, nry, nrz, dx, dy, dz);
        ppfs[t][2] = angle_f(ncx, ncy, ncz, nrx, nry, nrz);
        ppfs[t][3] = sqrtf(dx * dx + dy * dy + dz * dz + 1e-9f);
    }
    __syncthreads();

    // stage B: h = relu(ppf @ W1 + b1); thread: col c, 16 rows
    {
        int c = t & 63;
        int rg = t >> 6;
        float w0 = __ldg(&W1[0 * 64 + c]);
        float w1v = __ldg(&W1[1 * 64 + c]);
        float w2v = __ldg(&W1[2 * 64 + c]);
        float w3 = __ldg(&W1[3 * 64 + c]);
        float bb = __ldg(&b1[c]);
#pragma unroll
        for (int i = 0; i < 16; ++i) {
            int r = rg + 4 * i;
            float v = bb;
            v = fmaf(ppfs[r][0], w0, v);
            v = fmaf(ppfs[r][1], w1v, v);
            v = fmaf(ppfs[r][2], w2v, v);
            v = fmaf(ppfs[r][3], w3, v);
            hs[r][c] = fmaxf(v, 0.f);
        }
    }
    __syncthreads();

    // stage C: pe = h @ W2 + b2; 4x4 register tile per thread
    {
        int rg = t >> 4;          // 0..15 -> rows rg*4..rg*4+3
        int cg = t & 15;          // cols cg*4..cg*4+3
        float acc[4][4];
#pragma unroll
        for (int a = 0; a < 4; ++a)
#pragma unroll
            for (int b = 0; b < 4; ++b) acc[a][b] = 0.f;
        for (int k = 0; k < 64; ++k) {
            float4 wv = __ldg((const float4*)&W2[k * 64 + cg * 4]);
            float h0 = hs[rg * 4 + 0][k];
            float h1 = hs[rg * 4 + 1][k];
            float h2 = hs[rg * 4 + 2][k];
            float h3 = hs[rg * 4 + 3][k];
            acc[0][0] = fmaf(h0, wv.x, acc[0][0]); acc[0][1] = fmaf(h0, wv.y, acc[0][1]);
            acc[0][2] = fmaf(h0, wv.z, acc[0][2]); acc[0][3] = fmaf(h0, wv.w, acc[0][3]);
            acc[1][0] = fmaf(h1, wv.x, acc[1][0]); acc[1][1] = fmaf(h1, wv.y, acc[1][1]);
            acc[1][2] = fmaf(h1, wv.z, acc[1][2]); acc[1][3] = fmaf(h1, wv.w, acc[1][3]);
            acc[2][0] = fmaf(h2, wv.x, acc[2][0]); acc[2][1] = fmaf(h2, wv.y, acc[2][1]);
            acc[2][2] = fmaf(h2, wv.z, acc[2][2]); acc[2][3] = fmaf(h2, wv.w, acc[2][3]);
            acc[3][0] = fmaf(h3, wv.x, acc[3][0]); acc[3][1] = fmaf(h3, wv.y, acc[3][1]);
            acc[3][2] = fmaf(h3, wv.z, acc[3][2]); acc[3][3] = fmaf(h3, wv.w, acc[3][3]);
        }
        float4 bv = __ldg((const float4*)&b2[cg * 4]);
#pragma unroll
        for (int a = 0; a < 4; ++a) {
            int row = base + rg * 4 + a;
            float4 o;
            o.x = acc[a][0] + bv.x; o.y = acc[a][1] + bv.y;
            o.z = acc[a][2] + bv.z; o.w = acc[a][3] + bv.w;
            *(float4*)&g_pe[row * 64 + cg * 4] = o;
        }
    }
}

// ---------------- kernel 5: attention + Wo + LN + residual + relu ----------------
__global__ void __launch_bounds__(256) k_attn(const float* __restrict__ x,
                                              const float* __restrict__ Wo,
                                              const float* __restrict__ lng,
                                              const float* __restrict__ lnb,
                                              float* __restrict__ out) {
    __shared__ float vbuf[4][16][64];
    __shared__ float sl[4][4][16];
    __shared__ float wb[4][4][16];
    __shared__ float obuf[4][64];
    __shared__ float redA[4][2], redB[4][2];
    __shared__ int sidx[4][16];

    int pt = threadIdx.x >> 6;
    int t = threadIdx.x & 63;
    int n = blockIdx.x * 4 + pt;
    int h = t >> 4;

    if (t < 16) sidx[pt][t] = g_idx[n * KNN + t];
    __syncthreads();

    float qv = g_xq[n * 64 + t];

    for (int kk = 0; kk < 16; ++kk) {
        int j = sidx[pt][kk];
        float pe = g_pe[(n * KNN + kk) * 64 + t];
        float kvv = g_xk[j * 64 + t] + pe;
        float vvv = g_xv[j * 64 + t] + pe;
        vbuf[pt][kk][t] = vvv;
        float prod = qv * kvv;
#pragma unroll
        for (int off = 8; off; off >>= 1)
            prod += __shfl_xor_sync(0xffffffffu, prod, off);
        if ((t & 15) == 0) sl[pt][h][kk] = prod;
    }
    __syncthreads();

    if (t < 4) {
        float mx = -1e30f;
        float e[16];
#pragma unroll
        for (int kk = 0; kk < 16; ++kk) {
            float v = sl[pt][t][kk] * 0.25f;
            e[kk] = v;
            mx = fmaxf(mx, v);
        }
        float s = 0.f;
#pragma unroll
        for (int kk = 0; kk < 16; ++kk) { e[kk] = expf(e[kk] - mx); s += e[kk]; }
        float inv = 1.f / s;
#pragma unroll
        for (int kk = 0; kk < 16; ++kk) wb[pt][t][kk] = e[kk] * inv;
    }
    __syncthreads();

    float o = 0.f;
#pragma unroll
    for (int kk = 0; kk < 16; ++kk)
        o = fmaf(wb[pt][h][kk], vbuf[pt][kk][t], o);
    obuf[pt][t] = o;
    __syncthreads();

    float y = 0.f;
#pragma unroll 8
    for (int c = 0; c < 64; ++c)
        y = fmaf(obuf[pt][c], __ldg(&Wo[c * 64 + t]), y);

    // LayerNorm over 64 channels (2 warps per point)
    float s1 = y, s2 = y * y;
#pragma unroll
    for (int off = 16; off; off >>= 1) {
        s1 += __shfl_xor_sync(0xffffffffu, s1, off);
        s2 += __shfl_xor_sync(0xffffffffu, s2, off);
    }
    int wip = t >> 5;
    if ((t & 31) == 0) { redA[pt][wip] = s1; redB[pt][wip] = s2; }
    __syncthreads();
    float sum = redA[pt][0] + redA[pt][1];
    float sumsq = redB[pt][0] + redB[pt][1];
    float mu = sum * (1.f / 64.f);
    float var = fmaxf(sumsq * (1.f / 64.f) - mu * mu, 0.f);
    float yn = (y - mu) * rsqrtf(var + 1e-5f) * __ldg(&lng[t]) + __ldg(&lnb[t]);
    float res = yn + x[n * 64 + t];
    out[n * 64 + t] = fmaxf(res, 0.f);
}

// ---------------- launch ----------------
extern "C" void kernel_launch(void* const* d_in, const int* in_sizes, int n_in,
                              void* d_out, int out_size) {
    const float* p    = (const float*)d_in[0];
    const float* x    = (const float*)d_in[1];
    const float* nrm  = (const float*)d_in[2];
    const float* Wq   = (const float*)d_in[3];
    const float* Wk   = (const float*)d_in[4];
    const float* Wv   = (const float*)d_in[5];
    const float* Wo   = (const float*)d_in[6];
    const float* w1   = (const float*)d_in[7];
    const float* b1   = (const float*)d_in[8];
    const float* w2   = (const float*)d_in[9];
    const float* b2   = (const float*)d_in[10];
    const float* lng  = (const float*)d_in[11];
    const float* lnb  = (const float*)d_in[12];
    float* out = (float*)d_out;

    k_prep<<<NPTS / 256, 256>>>(p);
    k_proj<<<NPTS / 64, 256>>>(x, Wq, Wk, Wv);
    k_knn<<<NPTS / 8, 256>>>();
    k_ppf<<<NPTS * KNN / 64, 256>>>(p, nrm, w1, b1, w2, b2);
    k_attn<<<NPTS / 4, 256>>>(x, Wo, lng, lnb, out);
}

// round 9
// speedup vs baseline: 3.2910x; 1.0383x over previous
#include <cuda_runtime.h>
#include <cuda_bf16.h>

#define NPTS 8192
#define CDIM 64
#define HEADS 4
#define KNN 16
#define DH 16
#define FULLMASK 0xffffffffu

// ---------------- scratch (device globals; no allocations allowed) ----------------
__device__ float4 g_p4[NPTS];                       // x,y,z,|p|^2
__device__ float  g_xq[NPTS * CDIM];
__device__ float  g_xk[NPTS * CDIM];
__device__ float  g_xv[NPTS * CDIM];
__device__ int    g_idx[NPTS * KNN];
__device__ float  g_pe[NPTS * KNN * CDIM];          // 32 MB

// ---------------- kernel 1: pack p + squared norm ----------------
__global__ void k_prep(const float* __restrict__ p) {
    int i = blockIdx.x * blockDim.x + threadIdx.x;
    if (i < NPTS) {
        float x = p[3 * i], y = p[3 * i + 1], z = p[3 * i + 2];
        float s = x * x;
        s += y * y;
        s += z * z;
        g_p4[i] = make_float4(x, y, z, s);
    }
}

// ---------------- kernel 2: xq = x@Wq, xk = x@Wk, xv = x@Wv ----------------
__global__ void __launch_bounds__(256) k_proj(const float* __restrict__ x,
                                              const float* __restrict__ Wq,
                                              const float* __restrict__ Wk,
                                              const float* __restrict__ Wv) {
    __shared__ float xs[64][65];
    int t = threadIdx.x;
    int row0 = blockIdx.x * 64;
    for (int i = t; i < 64 * 64; i += 256)
        xs[i >> 6][i & 63] = x[(row0 + (i >> 6)) * 64 + (i & 63)];
    __syncthreads();

    int c = t & 63;
    int rg = t >> 6;   // 0..3, rows rg*16 .. rg*16+15
    float aq[16], ak[16], av[16];
#pragma unroll
    for (int r = 0; r < 16; ++r) { aq[r] = 0.f; ak[r] = 0.f; av[r] = 0.f; }

    for (int k = 0; k < 64; ++k) {
        float wq = __ldg(&Wq[k * 64 + c]);
        float wk = __ldg(&Wk[k * 64 + c]);
        float wv = __ldg(&Wv[k * 64 + c]);
#pragma unroll
        for (int r = 0; r < 16; ++r) {
            float xv = xs[rg * 16 + r][k];
            aq[r] = fmaf(xv, wq, aq[r]);
            ak[r] = fmaf(xv, wk, ak[r]);
            av[r] = fmaf(xv, wv, av[r]);
        }
    }
#pragma unroll
    for (int r = 0; r < 16; ++r) {
        int row = row0 + rg * 16 + r;
        g_xq[row * 64 + c] = aq[r];
        g_xk[row * 64 + c] = ak[r];
        g_xv[row * 64 + c] = av[r];
    }
}

// ---------------- kernel 3: exact KNN top-16 via warp-distributed sorted list ----------------
// Lane l (l<16) holds the l-th smallest (key, d2) seen so far by the whole warp.
// Hot-path filter uses plain float compare d2 <= tau_d2 (superset of key < tau);
// insert path uses the exact 64-bit key -> g_idx bit-identical to full sort.
__device__ __forceinline__ unsigned order_float(float f) {
    unsigned b = __float_as_uint(f);
    return (b & 0x80000000u) ? ~b : (b | 0x80000000u);
}

#define KNN_TILE 512

__global__ void __launch_bounds__(256) k_knn() {
    __shared__ float4 cbuf[KNN_TILE];                // 8 KB candidate tile
    int lane = threadIdx.x & 31;
    int w = threadIdx.x >> 5;
    int t = threadIdx.x;
    int gw = blockIdx.x * 8 + w;                     // query id

    float4 q = g_p4[gw];
    unsigned long long best = ~0ULL;                 // distributed sorted list
    float bestd2 = __int_as_float(0x7f800000);       // +inf
    unsigned long long tau = ~0ULL;
    float tau_d2 = __int_as_float(0x7f800000);

    for (int tile = 0; tile < NPTS; tile += KNN_TILE) {
        __syncthreads();
        cbuf[t]       = __ldg(&g_p4[tile + t]);
        cbuf[t + 256] = __ldg(&g_p4[tile + t + 256]);
        __syncthreads();

#pragma unroll 8
        for (int u = 0; u < KNN_TILE / 32; ++u) {
            int j = tile + u * 32 + lane;
            float4 cnd = cbuf[u * 32 + lane];
            float dot = q.x * cnd.x;
            dot = fmaf(q.y, cnd.y, dot);
            dot = fmaf(q.z, cnd.z, dot);
            float d2 = fmaf(-2.0f, dot, q.w + cnd.w);

            unsigned pend = __ballot_sync(FULLMASK, d2 <= tau_d2);
            if (pend) {
                unsigned long long key =
                    ((unsigned long long)order_float(d2) << 32) | (unsigned)j;
                pend &= __ballot_sync(FULLMASK, key < tau);
                while (pend) {
                    int src = __ffs(pend) - 1;
                    unsigned long long vb = __shfl_sync(FULLMASK, key, src);
                    float vd = __shfl_sync(FULLMASK, d2, src);
                    unsigned long long upk = __shfl_up_sync(FULLMASK, best, 1);
                    float upd = __shfl_up_sync(FULLMASK, bestd2, 1);
                    bool lt = vb < best;
                    unsigned m = __ballot_sync(FULLMASK, lt);
                    int fl = __ffs(m) - 1;
                    if (lt) {
                        best = (lane == fl) ? vb : upk;
                        bestd2 = (lane == fl) ? vd : upd;
                    }
                    tau = __shfl_sync(FULLMASK, best, 15);
                    tau_d2 = __shfl_sync(FULLMASK, bestd2, 15);
                    pend &= pend - 1;
                    pend &= __ballot_sync(FULLMASK, key < tau);
                }
            }
        }
    }

    if (lane < KNN)
        g_idx[gw * KNN + lane] = (int)(unsigned)(best & 0xffffffffu);
}

// ---------------- kernel 4: PPF features + pe MLP ----------------
__device__ __forceinline__ float angle_f(float ux, float uy, float uz,
                                         float vx, float vy, float vz) {
    float cx = uy * vz - uz * vy;
    float cy = uz * vx - ux * vz;
    float cz = ux * vy - uy * vx;
    float s = sqrtf(cx * cx + cy * cy + cz * cz + 1e-9f);
    float c = ux * vx + uy * vy + uz * vz;
    return atan2f(s, c);
}

// block = 256 threads handles 64 (n,kk) rows
__global__ void __launch_bounds__(256) k_ppf(const float* __restrict__ p,
                                             const float* __restrict__ nrm,
                                             const float* __restrict__ W1,
                                             const float* __restrict__ b1,
                                             const float* __restrict__ W2,
                                             const float* __restrict__ b2) {
    __shared__ float ppfs[64][4];
    __shared__ __align__(16) float hs[64][68];   // 68: 16B-aligned rows, conflict-free
    int t = threadIdx.x;
    int base = blockIdx.x * 64;   // global row = n*16 + kk

    // stage A: PPF (threads 0..63, one row each)
    if (t < 64) {
        int gr = base + t;
        int n = gr >> 4;
        int j = g_idx[gr];
        float px = p[3 * n], py = p[3 * n + 1], pz = p[3 * n + 2];
        float dx = p[3 * j] - px, dy = p[3 * j + 1] - py, dz = p[3 * j + 2] - pz;
        float ncx = nrm[3 * n], ncy = nrm[3 * n + 1], ncz = nrm[3 * n + 2];
        float nrx = nrm[3 * j], nry = nrm[3 * j + 1], nrz = nrm[3 * j + 2];
        ppfs[t][0] = angle_f(ncx, ncy, ncz, dx, dy, dz);
        ppfs[t][1] = angle_f(nrx, nry, nrz, dx, dy, dz);
        ppfs[t][2] = angle_f(ncx, ncy, ncz, nrx, nry, nrz);
        ppfs[t][3] = sqrtf(dx * dx + dy * dy + dz * dz + 1e-9f);
    }
    __syncthreads();

    // stage B: h = relu(ppf @ W1 + b1); thread: col c, 16 rows
    {
        int c = t & 63;
        int rg = t >> 6;
        float w0 = __ldg(&W1[0 * 64 + c]);
        float w1v = __ldg(&W1[1 * 64 + c]);
        float w2v = __ldg(&W1[2 * 64 + c]);
        float w3 = __ldg(&W1[3 * 64 + c]);
        float bb = __ldg(&b1[c]);
#pragma unroll
        for (int i = 0; i < 16; ++i) {
            int r = rg + 4 * i;
            float v = bb;
            v = fmaf(ppfs[r][0], w0, v);
            v = fmaf(ppfs[r][1], w1v, v);
            v = fmaf(ppfs[r][2], w2v, v);
            v = fmaf(ppfs[r][3], w3, v);
            hs[r][c] = fmaxf(v, 0.f);
        }
    }
    __syncthreads();

    // stage C: pe = h @ W2 + b2; 4x4 register tile, LDS.128 for h chunks
    {
        int rg = t >> 4;          // 0..15 -> rows rg*4..rg*4+3
        int cg = t & 15;          // cols cg*4..cg*4+3
        float acc[4][4];
#pragma unroll
        for (int a = 0; a < 4; ++a)
#pragma unroll
            for (int b = 0; b < 4; ++b) acc[a][b] = 0.f;

        for (int k = 0; k < 64; k += 4) {
            float4 hv[4];
#pragma unroll
            for (int a = 0; a < 4; ++a)
                hv[a] = *(const float4*)&hs[rg * 4 + a][k];
            float4 wv[4];
#pragma unroll
            for (int kk = 0; kk < 4; ++kk)
                wv[kk] = __ldg((const float4*)&W2[(k + kk) * 64 + cg * 4]);
#pragma unroll
            for (int a = 0; a < 4; ++a) {
                acc[a][0] = fmaf(hv[a].x, wv[0].x, acc[a][0]);
                acc[a][1] = fmaf(hv[a].x, wv[0].y, acc[a][1]);
                acc[a][2] = fmaf(hv[a].x, wv[0].z, acc[a][2]);
                acc[a][3] = fmaf(hv[a].x, wv[0].w, acc[a][3]);
                acc[a][0] = fmaf(hv[a].y, wv[1].x, acc[a][0]);
                acc[a][1] = fmaf(hv[a].y, wv[1].y, acc[a][1]);
                acc[a][2] = fmaf(hv[a].y, wv[1].z, acc[a][2]);
                acc[a][3] = fmaf(hv[a].y, wv[1].w, acc[a][3]);
                acc[a][0] = fmaf(hv[a].z, wv[2].x, acc[a][0]);
                acc[a][1] = fmaf(hv[a].z, wv[2].y, acc[a][1]);
                acc[a][2] = fmaf(hv[a].z, wv[2].z, acc[a][2]);
                acc[a][3] = fmaf(hv[a].z, wv[2].w, acc[a][3]);
                acc[a][0] = fmaf(hv[a].w, wv[3].x, acc[a][0]);
                acc[a][1] = fmaf(hv[a].w, wv[3].y, acc[a][1]);
                acc[a][2] = fmaf(hv[a].w, wv[3].z, acc[a][2]);
                acc[a][3] = fmaf(hv[a].w, wv[3].w, acc[a][3]);
            }
        }
        float4 bv = __ldg((const float4*)&b2[cg * 4]);
#pragma unroll
        for (int a = 0; a < 4; ++a) {
            int row = base + rg * 4 + a;
            float4 o;
            o.x = acc[a][0] + bv.x; o.y = acc[a][1] + bv.y;
            o.z = acc[a][2] + bv.z; o.w = acc[a][3] + bv.w;
            *(float4*)&g_pe[row * 64 + cg * 4] = o;
        }
    }
}

// ---------------- kernel 5: attention + Wo + LN + residual + relu ----------------
__global__ void __launch_bounds__(256) k_attn(const float* __restrict__ x,
                                              const float* __restrict__ Wo,
                                              const float* __restrict__ lng,
                                              const float* __restrict__ lnb,
                                              float* __restrict__ out) {
    __shared__ float vbuf[4][16][64];
    __shared__ float sl[4][4][16];
    __shared__ float wb[4][4][16];
    __shared__ float obuf[4][64];
    __shared__ float redA[4][2], redB[4][2];
    __shared__ int sidx[4][16];

    int pt = threadIdx.x >> 6;
    int t = threadIdx.x & 63;
    int n = blockIdx.x * 4 + pt;
    int h = t >> 4;

    if (t < 16) sidx[pt][t] = g_idx[n * KNN + t];
    __syncthreads();

    float qv = g_xq[n * 64 + t];

    for (int kk = 0; kk < 16; ++kk) {
        int j = sidx[pt][kk];
        float pe = g_pe[(n * KNN + kk) * 64 + t];
        float kvv = g_xk[j * 64 + t] + pe;
        float vvv = g_xv[j * 64 + t] + pe;
        vbuf[pt][kk][t] = vvv;
        float prod = qv * kvv;
#pragma unroll
        for (int off = 8; off; off >>= 1)
            prod += __shfl_xor_sync(0xffffffffu, prod, off);
        if ((t & 15) == 0) sl[pt][h][kk] = prod;
    }
    __syncthreads();

    if (t < 4) {
        float mx = -1e30f;
        float e[16];
#pragma unroll
        for (int kk = 0; kk < 16; ++kk) {
            float v = sl[pt][t][kk] * 0.25f;
            e[kk] = v;
            mx = fmaxf(mx, v);
        }
        float s = 0.f;
#pragma unroll
        for (int kk = 0; kk < 16; ++kk) { e[kk] = expf(e[kk] - mx); s += e[kk]; }
        float inv = 1.f / s;
#pragma unroll
        for (int kk = 0; kk < 16; ++kk) wb[pt][t][kk] = e[kk] * inv;
    }
    __syncthreads();

    float o = 0.f;
#pragma unroll
    for (int kk = 0; kk < 16; ++kk)
        o = fmaf(wb[pt][h][kk], vbuf[pt][kk][t], o);
    obuf[pt][t] = o;
    __syncthreads();

    float y = 0.f;
#pragma unroll 8
    for (int c = 0; c < 64; ++c)
        y = fmaf(obuf[pt][c], __ldg(&Wo[c * 64 + t]), y);

    // LayerNorm over 64 channels (2 warps per point)
    float s1 = y, s2 = y * y;
#pragma unroll
    for (int off = 16; off; off >>= 1) {
        s1 += __shfl_xor_sync(0xffffffffu, s1, off);
        s2 += __shfl_xor_sync(0xffffffffu, s2, off);
    }
    int wip = t >> 5;
    if ((t & 31) == 0) { redA[pt][wip] = s1; redB[pt][wip] = s2; }
    __syncthreads();
    float sum = redA[pt][0] + redA[pt][1];
    float sumsq = redB[pt][0] + redB[pt][1];
    float mu = sum * (1.f / 64.f);
    float var = fmaxf(sumsq * (1.f / 64.f) - mu * mu, 0.f);
    float yn = (y - mu) * rsqrtf(var + 1e-5f) * __ldg(&lng[t]) + __ldg(&lnb[t]);
    float res = yn + x[n * 64 + t];
    out[n * 64 + t] = fmaxf(res, 0.f);
}

// ---------------- launch ----------------
extern "C" void kernel_launch(void* const* d_in, const int* in_sizes, int n_in,
                              void* d_out, int out_size) {
    const float* p    = (const float*)d_in[0];
    const float* x    = (const float*)d_in[1];
    const float* nrm  = (const float*)d_in[2];
    const float* Wq   = (const float*)d_in[3];
    const float* Wk   = (const float*)d_in[4];
    const float* Wv   = (const float*)d_in[5];
    const float* Wo   = (const float*)d_in[6];
    const float* w1   = (const float*)d_in[7];
    const float* b1   = (const float*)d_in[8];
    const float* w2   = (const float*)d_in[9];
    const float* b2   = (const float*)d_in[10];
    const float* lng  = (const float*)d_in[11];
    const float* lnb  = (const float*)d_in[12];
    float* out = (float*)d_out;

    k_prep<<<NPTS / 256, 256>>>(p);
    k_proj<<<NPTS / 64, 256>>>(x, Wq, Wk, Wv);
    k_knn<<<NPTS / 8, 256>>>();
    k_ppf<<<NPTS * KNN / 64, 256>>>(p, nrm, w1, b1, w2, b2);
    k_attn<<<NPTS / 4, 256>>>(x, Wo, lng, lnb, out);
}